// round 13
// baseline (speedup 1.0000x reference)
#include <cuda_runtime.h>
#include <cuda_bf16.h>
#include <cstdint>

#define BB 8
#define CC 128
#define WW 4096
#define DD 16

// 0.25 (= D^-0.5) * log2(e): folded into q so softmax uses exp2 directly.
#define QSCALE 0.3606737602222409f

typedef unsigned long long ull;

// ---- scratch (__device__ globals; no allocs allowed) ----------------------
__device__ __nv_bfloat16 g_q[(size_t)BB*WW*DD];   // [b][w][d], pre-scaled
__device__ __nv_bfloat16 g_k[(size_t)BB*WW*DD];   // [b][w][d]
__device__ __nv_bfloat16 g_v[(size_t)BB*CC*WW];   // [b][c][w]; later scaled by linv[j]

// ---- helpers --------------------------------------------------------------
__device__ __forceinline__ uint32_t smem_u32(const void* p) {
    uint32_t a;
    asm("{ .reg .u64 t; cvta.to.shared.u64 t, %1; cvt.u32.u64 %0, t; }"
        : "=r"(a) : "l"(p));
    return a;
}
__device__ __forceinline__ uint32_t bf2u(__nv_bfloat162 h) {
    return *reinterpret_cast<uint32_t*>(&h);
}

// ---- mma.sync m16n8k16 bf16 (A row-major, B col-major, f32 accum) ---------
__device__ __forceinline__ void mma_acc(float* d, const uint32_t* a,
                                        uint32_t b0, uint32_t b1) {
    asm volatile("mma.sync.aligned.m16n8k16.row.col.f32.bf16.bf16.f32 "
        "{%0,%1,%2,%3}, {%4,%5,%6,%7}, {%8,%9}, {%0,%1,%2,%3};"
        : "+f"(d[0]), "+f"(d[1]), "+f"(d[2]), "+f"(d[3])
        : "r"(a[0]), "r"(a[1]), "r"(a[2]), "r"(a[3]), "r"(b0), "r"(b1));
}
__device__ __forceinline__ void mma_z(float* d, const uint32_t* a,
                                      uint32_t b0, uint32_t b1) {
    asm volatile("mma.sync.aligned.m16n8k16.row.col.f32.bf16.bf16.f32 "
        "{%0,%1,%2,%3}, {%4,%5,%6,%7}, {%8,%9}, {%10,%10,%10,%10};"
        : "=f"(d[0]), "=f"(d[1]), "=f"(d[2]), "=f"(d[3])
        : "r"(a[0]), "r"(a[1]), "r"(a[2]), "r"(a[3]), "r"(b0), "r"(b1),
          "f"(0.0f));
}
#define LDMX4(v0, v1, v2, v3, addr) \
    asm volatile("ldmatrix.sync.aligned.m8n8.x4.shared.b16 {%0,%1,%2,%3}, [%4];" \
        : "=r"(v0), "=r"(v1), "=r"(v2), "=r"(v3) : "r"(addr))

// ---- cp.async -------------------------------------------------------------
#define CP16(dst, src) asm volatile("cp.async.cg.shared.global [%0], [%1], 16;" :: "r"(dst), "l"(src))
#define CP8(dst, src)  asm volatile("cp.async.ca.shared.global [%0], [%1], 8;"  :: "r"(dst), "l"(src))
#define CP_COMMIT()    asm volatile("cp.async.commit_group;" ::: "memory")
#define CP_WAIT0()     asm volatile("cp.async.wait_group 0;" ::: "memory")
#define CP_WAIT1()     asm volatile("cp.async.wait_group 1;" ::: "memory")

// ===========================================================================
// Kernel 1: projections via bf16 HMMA. 64-wide w tiles (512 CTAs, 65.5KB
// smem -> 3 CTAs/SM) for latency hiding of the serial load->mma phases.
// ===========================================================================
#define SPX 272
#define SPT 144
#define P_OFX 0         // xT: 64 x 272     = 17408
#define P_OFW 17408     // Wv: 128 x 272    = 34816
#define P_OFQ 52224     // Wqk: 32 x 272    = 8704
#define P_OFT 60928     // qkT: 32 x 144    = 4608  -> total 65536

__global__ void __launch_bounds__(256) k_proj(
    const float* __restrict__ x,
    const float* __restrict__ Wq, const float* __restrict__ bq,
    const float* __restrict__ Wk, const float* __restrict__ bk,
    const float* __restrict__ Wv, const float* __restrict__ bv)
{
    extern __shared__ __align__(16) char smc[];
    const int b   = blockIdx.y;
    const int w0  = blockIdx.x * 64;
    const int tid = threadIdx.x;
    const int wid = tid >> 5;
    const int lane = tid & 31;
    const int g = lane >> 2, t = lane & 3;

    for (int i = tid; i < 128*32; i += 256) {
        int r = i >> 5, cf = i & 31;
        float4 v = *(const float4*)(Wv + r*128 + cf*4);
        uint2 o;
        o.x = bf2u(__floats2bfloat162_rn(v.x, v.y));
        o.y = bf2u(__floats2bfloat162_rn(v.z, v.w));
        *(uint2*)(smc + P_OFW + r*SPX + cf*8) = o;
    }
    for (int i = tid; i < 32*32; i += 256) {
        int r = i >> 5, cf = i & 31;
        const float* src = (r < 16) ? (Wq + r*128 + cf*4) : (Wk + (r-16)*128 + cf*4);
        float4 v = *(const float4*)src;
        uint2 o;
        o.x = bf2u(__floats2bfloat162_rn(v.x, v.y));
        o.y = bf2u(__floats2bfloat162_rn(v.z, v.w));
        *(uint2*)(smc + P_OFQ + r*SPX + cf*8) = o;
    }
    // ---- x -> xT[w][c] bf16: thread owns c-pair, 32-bit conflict-free ----
    {
        const int c2 = tid & 63;         // c = 2*c2
        const int wg = tid >> 6;         // 0..3 -> w-range wg*16..+15
        #pragma unroll
        for (int chunk = 0; chunk < 2; chunk++) {
            const int wb = wg*16 + chunk*8;
            const float* xp0 = x + (size_t)(b*CC + 2*c2)*WW + w0 + wb;
            const float* xp1 = xp0 + WW;
            float4 a0 = *(const float4*)xp0;
            float4 a1 = *(const float4*)(xp0 + 4);
            float4 c0 = *(const float4*)xp1;
            float4 c1 = *(const float4*)(xp1 + 4);
            char* base = smc + P_OFX + c2*4;
            *(uint32_t*)(base + (wb  )*SPX) = bf2u(__floats2bfloat162_rn(a0.x, c0.x));
            *(uint32_t*)(base + (wb+1)*SPX) = bf2u(__floats2bfloat162_rn(a0.y, c0.y));
            *(uint32_t*)(base + (wb+2)*SPX) = bf2u(__floats2bfloat162_rn(a0.z, c0.z));
            *(uint32_t*)(base + (wb+3)*SPX) = bf2u(__floats2bfloat162_rn(a0.w, c0.w));
            *(uint32_t*)(base + (wb+4)*SPX) = bf2u(__floats2bfloat162_rn(a1.x, c1.x));
            *(uint32_t*)(base + (wb+5)*SPX) = bf2u(__floats2bfloat162_rn(a1.y, c1.y));
            *(uint32_t*)(base + (wb+6)*SPX) = bf2u(__floats2bfloat162_rn(a1.z, c1.z));
            *(uint32_t*)(base + (wb+7)*SPX) = bf2u(__floats2bfloat162_rn(a1.w, c1.w));
        }
    }
    __syncthreads();

    {   // V GEMM: warp = 16 c_out rows x 64 w (8 n-tiles)
        const int mb = wid * 16;
        uint32_t A[8][4];
        #pragma unroll
        for (int kt = 0; kt < 8; kt++) {
            const char* r0 = smc + P_OFW + (mb + g)*SPX + kt*32 + t*4;
            const char* r1 = smc + P_OFW + (mb + g + 8)*SPX + kt*32 + t*4;
            A[kt][0] = *(const uint32_t*)r0;
            A[kt][1] = *(const uint32_t*)r1;
            A[kt][2] = *(const uint32_t*)(r0 + 16);
            A[kt][3] = *(const uint32_t*)(r1 + 16);
        }
        const float bias0 = bv[mb + g], bias1 = bv[mb + g + 8];
        #pragma unroll
        for (int nt = 0; nt < 8; nt++) {
            float acc[4] = {bias0, bias0, bias1, bias1};
            #pragma unroll
            for (int kt = 0; kt < 8; kt++) {
                const char* bp = smc + P_OFX + (nt*8 + g)*SPX + kt*32 + t*4;
                uint32_t b0 = *(const uint32_t*)bp;
                uint32_t b1 = *(const uint32_t*)(bp + 16);
                mma_acc(acc, A[kt], b0, b1);
            }
            const int wcol = w0 + nt*8 + 2*t;
            *(uint32_t*)(g_v + (size_t)(b*CC + mb + g)*WW + wcol) =
                bf2u(__floats2bfloat162_rn(acc[0], acc[1]));
            *(uint32_t*)(g_v + (size_t)(b*CC + mb + g + 8)*WW + wcol) =
                bf2u(__floats2bfloat162_rn(acc[2], acc[3]));
        }
    }

    {   // QK GEMM: warp m-tile = wid&1, n-tiles [(wid>>1)*2, +2)
        const int mt = wid & 1, ntb = (wid >> 1) * 2;
        uint32_t A[8][4];
        #pragma unroll
        for (int kt = 0; kt < 8; kt++) {
            const char* r0 = smc + P_OFQ + (mt*16 + g)*SPX + kt*32 + t*4;
            const char* r1 = smc + P_OFQ + (mt*16 + g + 8)*SPX + kt*32 + t*4;
            A[kt][0] = *(const uint32_t*)r0;
            A[kt][1] = *(const uint32_t*)r1;
            A[kt][2] = *(const uint32_t*)(r0 + 16);
            A[kt][3] = *(const uint32_t*)(r1 + 16);
        }
        const float* bias = mt ? bk : bq;
        const float bias0 = bias[g], bias1 = bias[g + 8];
        const float psc = mt ? 1.0f : QSCALE;
        #pragma unroll
        for (int nt = ntb; nt < ntb + 2; nt++) {
            float acc[4] = {bias0, bias0, bias1, bias1};
            #pragma unroll
            for (int kt = 0; kt < 8; kt++) {
                const char* bp = smc + P_OFX + (nt*8 + g)*SPX + kt*32 + t*4;
                uint32_t b0 = *(const uint32_t*)bp;
                uint32_t b1 = *(const uint32_t*)(bp + 16);
                mma_acc(acc, A[kt], b0, b1);
            }
            const int wcol = nt*8 + 2*t;
            *(uint32_t*)(smc + P_OFT + (mt*16 + g)*SPT + wcol*2) =
                bf2u(__floats2bfloat162_rn(acc[0]*psc, acc[1]*psc));
            *(uint32_t*)(smc + P_OFT + (mt*16 + g + 8)*SPT + wcol*2) =
                bf2u(__floats2bfloat162_rn(acc[2]*psc, acc[3]*psc));
        }
    }
    __syncthreads();

    if (tid < 128) {   // transpose qkT -> g_q/g_k [w][16]
        const int w = tid & 63, half = tid >> 6;
        uint32_t u[8];
        #pragma unroll
        for (int i = 0; i < 8; i++) {
            uint32_t lo = *(const uint16_t*)(smc + P_OFT + (half*16 + 2*i    )*SPT + w*2);
            uint32_t hi = *(const uint16_t*)(smc + P_OFT + (half*16 + 2*i + 1)*SPT + w*2);
            u[i] = lo | (hi << 16);
        }
        __nv_bfloat16* op = (half ? g_k : g_q) + (size_t)(b*WW + w0 + w)*DD;
        *(uint4*)op       = make_uint4(u[0], u[1], u[2], u[3]);
        *(uint4*)(op + 8) = make_uint4(u[4], u[5], u[6], u[7]);
    }
}

// ===========================================================================
// Kernel 2: row sums + fold 1/l into V.  WARP-AUTONOMOUS: each warp owns a
// private w-slice (16 w per iter, own k rows, own cp.async group) -> no
// __syncthreads in the main loop.  (R11 bug fixed: prefetch dst buffer
// offset was double-added for odd iterations, stomping the next warp's k.)
// ===========================================================================
#define SKD 48
__global__ void __launch_bounds__(256, 2) k_stats()
{
    __shared__ __align__(16) char smq[128*SKD];          // q: all 128 j rows
    __shared__ __align__(16) char smk[8*2*16*SKD];       // per-warp k dbl-buf
    __shared__ float partial[8][128];
    __shared__ float red[128];
    __shared__ uint32_t lpk[64];
    const uint32_t QS = smem_u32(smq);
    const uint32_t KB = smem_u32(smk);
    const int tid = threadIdx.x;
    const int wid = tid >> 5;
    const int lane = tid & 31;
    const int g = lane >> 2, t = lane & 3;
    const int b = blockIdx.y, j0 = blockIdx.x * 128;

    const uint32_t kw = KB + wid*(2*16*SKD);
    const uint32_t kldst = kw + (lane >> 1)*SKD + (lane & 1)*16;
    const uint32_t mlane16 = (uint32_t)((((lane >> 4)*8 + (lane & 7))*SKD)
                                        + ((lane >> 3) & 1)*16);

    {   // q tile (block-shared), k tile it=0 (warp-private)
        int r = tid >> 1, h = tid & 1;
        CP16(QS + r*SKD + h*16, (const char*)(g_q + (size_t)(b*WW + j0 + r)*DD) + h*16);
        CP16(kldst, (const char*)(g_k + (size_t)(b*WW + wid*16 + (lane >> 1))*DD)
                    + (lane & 1)*16);
    }
    CP_COMMIT(); CP_WAIT0();
    __syncthreads();   // q visible to all warps; no more block syncs until end

    // A fragments: 8 j m-tiles, loaded once
    uint32_t A[8][4];
    #pragma unroll
    for (int mt = 0; mt < 8; mt++) {
        const char* r0 = smq + (mt*16 + g)*SKD + t*4;
        const char* r1 = smq + (mt*16 + g + 8)*SKD + t*4;
        A[mt][0] = *(const uint32_t*)r0;
        A[mt][1] = *(const uint32_t*)r1;
        A[mt][2] = *(const uint32_t*)(r0 + 16);
        A[mt][3] = *(const uint32_t*)(r1 + 16);
    }

    float lacc[8][2];
    #pragma unroll
    for (int mt = 0; mt < 8; mt++) { lacc[mt][0] = 0.0f; lacc[mt][1] = 0.0f; }

    for (int it8 = 0; it8 < 4; it8++) {
        uint32_t acc01[8], acc23[8];
        #pragma unroll
        for (int mt = 0; mt < 8; mt++) { acc01[mt] = 0u; acc23[mt] = 0u; }
        #pragma unroll
        for (int i8 = 0; i8 < 8; i8++) {
            const int it = it8*8 + i8;
            if (it + 1 < 32) {   // prefetch own next k slice into buffer (it+1)&1
                CP16(kldst + (uint32_t)(((it + 1) & 1)*(16*SKD)),
                     (const char*)(g_k + (size_t)(b*WW + (it + 1)*128 + wid*16
                                                  + (lane >> 1))*DD) + (lane & 1)*16);
            }
            CP_COMMIT();
            CP_WAIT1();          // own buffer it&1 ready
            uint32_t v0, v1, v2, v3;
            LDMX4(v0, v1, v2, v3, kw + (uint32_t)((it & 1)*(16*SKD)) + mlane16);
            #pragma unroll
            for (int mt = 0; mt < 8; mt++) {
                float d[4];
                uint32_t h01, h23;
                mma_z(d, A[mt], v0, v1);
                asm("cvt.rn.f16x2.f32 %0, %1, %2;" : "=r"(h01) : "f"(d[1]), "f"(d[0]));
                asm("cvt.rn.f16x2.f32 %0, %1, %2;" : "=r"(h23) : "f"(d[3]), "f"(d[2]));
                asm("ex2.approx.f16x2 %0, %0;" : "+r"(h01));
                asm("ex2.approx.f16x2 %0, %0;" : "+r"(h23));
                asm("add.rn.f16x2 %0, %0, %1;" : "+r"(acc01[mt]) : "r"(h01));
                asm("add.rn.f16x2 %0, %0, %1;" : "+r"(acc23[mt]) : "r"(h23));
                mma_z(d, A[mt], v2, v3);
                asm("cvt.rn.f16x2.f32 %0, %1, %2;" : "=r"(h01) : "f"(d[1]), "f"(d[0]));
                asm("cvt.rn.f16x2.f32 %0, %1, %2;" : "=r"(h23) : "f"(d[3]), "f"(d[2]));
                asm("ex2.approx.f16x2 %0, %0;" : "+r"(h01));
                asm("ex2.approx.f16x2 %0, %0;" : "+r"(h23));
                asm("add.rn.f16x2 %0, %0, %1;" : "+r"(acc01[mt]) : "r"(h01));
                asm("add.rn.f16x2 %0, %0, %1;" : "+r"(acc23[mt]) : "r"(h23));
            }
        }
        // flush pair accumulators to f32 (16 half-adds per half per flush)
        #pragma unroll
        for (int mt = 0; mt < 8; mt++) {
            float f0, f1, f2, f3;
            asm("{.reg .f16 lo, hi; mov.b32 {lo, hi}, %2; cvt.f32.f16 %0, lo; cvt.f32.f16 %1, hi;}"
                : "=f"(f0), "=f"(f1) : "r"(acc01[mt]));
            asm("{.reg .f16 lo, hi; mov.b32 {lo, hi}, %2; cvt.f32.f16 %0, lo; cvt.f32.f16 %1, hi;}"
                : "=f"(f2), "=f"(f3) : "r"(acc23[mt]));
            lacc[mt][0] += f0 + f1;
            lacc[mt][1] += f2 + f3;
        }
    }

    // reduce across the 4 lanes sharing each row, then across warps
    #pragma unroll
    for (int mt = 0; mt < 8; mt++) {
        #pragma unroll
        for (int off = 1; off < 4; off <<= 1) {
            lacc[mt][0] += __shfl_down_sync(0xffffffffu, lacc[mt][0], off, 4);
            lacc[mt][1] += __shfl_down_sync(0xffffffffu, lacc[mt][1], off, 4);
        }
        if (t == 0) {
            partial[wid][mt*16 + g]     = lacc[mt][0];
            partial[wid][mt*16 + g + 8] = lacc[mt][1];
        }
    }
    __syncthreads();
    if (tid < 128) {
        float l = partial[0][tid] + partial[1][tid] + partial[2][tid] + partial[3][tid]
                + partial[4][tid] + partial[5][tid] + partial[6][tid] + partial[7][tid];
        red[tid] = 1.0f / l;
    }
    __syncthreads();
    if (tid < 64)
        lpk[tid] = bf2u(__floats2bfloat162_rn(red[2*tid], red[2*tid + 1]));
    __syncthreads();

    // ---- scale g_v[:, j0:j0+128] by 1/l (in place, bf16x2 muls) ----
    {
        const int chunk = tid & 15;
        const int cb    = tid >> 4;
        uint32_t s0 = lpk[chunk*4], s1 = lpk[chunk*4 + 1];
        uint32_t s2 = lpk[chunk*4 + 2], s3 = lpk[chunk*4 + 3];
        #pragma unroll
        for (int c = cb; c < 128; c += 16) {
            uint32_t* vp = (uint32_t*)(g_v + (size_t)(b*CC + c)*WW + j0 + chunk*8);
            uint4 v = *(uint4*)vp;
            asm("mul.rn.bf16x2 %0, %0, %1;" : "+r"(v.x) : "r"(s0));
            asm("mul.rn.bf16x2 %0, %0, %1;" : "+r"(v.y) : "r"(s1));
            asm("mul.rn.bf16x2 %0, %0, %1;" : "+r"(v.z) : "r"(s2));
            asm("mul.rn.bf16x2 %0, %0, %1;" : "+r"(v.w) : "r"(s3));
            *(uint4*)vp = v;
        }
    }
}

// ===========================================================================
// Kernel 3: context + residual (unchanged from R10 — protect the win).
// ===========================================================================
#define SPJ 144
#define OF_KS 0
#define OF_QR 6144
#define OF_VS 18432

__global__ void __launch_bounds__(256, 2) k_ctx(const float* __restrict__ x,
                                                float* __restrict__ out)
{
    extern __shared__ __align__(16) char smc[];
    const uint32_t smb = smem_u32(smc);
    const int tid = threadIdx.x;
    const int wid = tid >> 5;
    const int lane = tid & 31;
    const int g = lane >> 2, t = lane & 3;
    const int b = blockIdx.y, w0 = blockIdx.x * 128;

    {
        int r = tid >> 1, h = tid & 1;
        CP16(smb + OF_KS + r*SKD + h*16,
             (const char*)(g_k + (size_t)(b*WW + w0 + r)*DD) + h*16);
    }
    {
        int r = tid >> 2, h = tid & 3;
        CP8(smb + OF_QR + r*SKD + h*8,
            (const char*)(g_q + (size_t)(b*WW + r)*DD) + h*8);
        CP8(smb + OF_QR + 3072 + r*SKD + h*8,
            (const char*)(g_q + (size_t)(b*WW + 64 + r)*DD) + h*8);
    }
    #pragma unroll
    for (int i = 0; i < 4; i++) {
        int cid = tid + i*256;
        int c = cid >> 3, ch = cid & 7;
        CP16(smb + OF_VS + c*SPJ + ch*16,
             (const char*)(g_v + (size_t)(b*CC + c)*WW) + ch*16);
    }
    CP_COMMIT(); CP_WAIT0();
    __syncthreads();

    uint32_t ak[4];
    {
        const char* r0 = smc + OF_KS + (wid*16 + g)*SKD + t*4;
        const char* r1 = smc + OF_KS + (wid*16 + g + 8)*SKD + t*4;
        ak[0] = *(const uint32_t*)r0;
        ak[1] = *(const uint32_t*)r1;
        ak[2] = *(const uint32_t*)(r0 + 16);
        ak[3] = *(const uint32_t*)(r1 + 16);
    }

    const uint32_t vlane = (uint32_t)((((lane >> 4)*8 + (lane & 7))*SPJ)
                                      + ((lane >> 3) & 1)*16);
    const uint32_t qlane = (uint32_t)((((lane >> 4)*8 + (lane & 7))*SKD)
                                      + ((lane >> 3) & 1)*16);

    float acc[16][4];
    #pragma unroll
    for (int ct = 0; ct < 16; ct++)
        #pragma unroll
        for (int e = 0; e < 4; e++) acc[ct][e] = 0.0f;

    for (int jt = 0; jt < 64; jt++) {
        if (jt + 2 < 64) {
            int r = tid >> 2, h = tid & 3;
            CP8(smb + OF_QR + ((jt + 2) & 3)*3072 + r*SKD + h*8,
                (const char*)(g_q + (size_t)(b*WW + (jt + 2)*64 + r)*DD) + h*8);
        }
        if (jt + 1 < 64) {
            #pragma unroll
            for (int i = 0; i < 4; i++) {
                int cid = tid + i*256;
                int c = cid >> 3, ch = cid & 7;
                CP16(smb + OF_VS + ((jt + 1) & 1)*18432 + c*SPJ + ch*16,
                     (const char*)(g_v + (size_t)(b*CC + c)*WW + (jt + 1)*64) + ch*16);
            }
        }
        CP_COMMIT();

        const uint32_t qb = smb + OF_QR + (jt & 3)*3072 + qlane;
        const uint32_t vb = smb + OF_VS + (jt & 1)*18432 + vlane;

        #pragma unroll
        for (int ks = 0; ks < 4; ks++) {
            uint32_t A[4];
            {
                uint32_t q0, q1, q2, q3;
                LDMX4(q0, q1, q2, q3, qb + (uint32_t)(ks*(16*SKD)));
                float d[4];
                mma_z(d, ak, q0, q1);
                asm("cvt.rn.bf16x2.f32 %0, %1, %2;" : "=r"(A[0]) : "f"(d[1]), "f"(d[0]));
                asm("cvt.rn.bf16x2.f32 %0, %1, %2;" : "=r"(A[1]) : "f"(d[3]), "f"(d[2]));
                mma_z(d, ak, q2, q3);
                asm("cvt.rn.bf16x2.f32 %0, %1, %2;" : "=r"(A[2]) : "f"(d[1]), "f"(d[0]));
                asm("cvt.rn.bf16x2.f32 %0, %1, %2;" : "=r"(A[3]) : "f"(d[3]), "f"(d[2]));
                asm("ex2.approx.ftz.bf16x2 %0, %0;" : "+r"(A[0]));
                asm("ex2.approx.ftz.bf16x2 %0, %0;" : "+r"(A[1]));
                asm("ex2.approx.ftz.bf16x2 %0, %0;" : "+r"(A[2]));
                asm("ex2.approx.ftz.bf16x2 %0, %0;" : "+r"(A[3]));
            }
            #pragma unroll
            for (int cp = 0; cp < 8; cp++) {
                uint32_t v0, v1, v2, v3;
                uint32_t ad = vb + (uint32_t)(cp*(16*SPJ) + ks*32);
                LDMX4(v0, v1, v2, v3, ad);
                mma_acc(acc[2*cp],     A, v0, v1);
                mma_acc(acc[2*cp + 1], A, v2, v3);
            }
        }
        CP_WAIT0();
        __syncthreads();
    }

    const int wbase = w0 + wid*16;
    #pragma unroll
    for (int ct = 0; ct < 16; ct++) {
        size_t base = (size_t)(b*CC + ct*8 + 2*t)*WW + wbase;
        out[base + g]          = acc[ct][0] + x[base + g];
        out[base + g + 8]      = acc[ct][2] + x[base + g + 8];
        out[base + WW + g]     = acc[ct][1] + x[base + WW + g];
        out[base + WW + g + 8] = acc[ct][3] + x[base + WW + g + 8];
    }
}

// ===========================================================================
extern "C" void kernel_launch(void* const* d_in, const int* in_sizes, int n_in,
                              void* d_out, int out_size)
{
    const float* x  = (const float*)d_in[0];
    const float* Wq = (const float*)d_in[1];
    const float* bq = (const float*)d_in[2];
    const float* Wk = (const float*)d_in[3];
    const float* bk = (const float*)d_in[4];
    const float* Wv = (const float*)d_in[5];
    const float* bv = (const float*)d_in[6];
    float* out = (float*)d_out;

    const int smem_proj = 65536;
    const int smem_ctx  = 55296;
    cudaFuncSetAttribute(k_proj, cudaFuncAttributeMaxDynamicSharedMemorySize, smem_proj);
    cudaFuncSetAttribute(k_ctx,  cudaFuncAttributeMaxDynamicSharedMemorySize, smem_ctx);

    dim3 g1(WW/64, BB);
    k_proj <<<g1, 256, smem_proj>>>(x, Wq, bq, Wk, bk, Wv, bv);
    dim3 g2(WW/128, BB);
    k_stats<<<g2, 256>>>();
    k_ctx  <<<g2, 256, smem_ctx>>>(x, out);
}

// round 14
// speedup vs baseline: 1.0284x; 1.0284x over previous
#include <cuda_runtime.h>
#include <cuda_bf16.h>
#include <cstdint>

#define BB 8
#define CC 128
#define WW 4096
#define DD 16

// 0.25 (= D^-0.5) * log2(e): folded into q so softmax uses exp2 directly.
#define QSCALE 0.3606737602222409f

typedef unsigned long long ull;

// ---- scratch (__device__ globals; no allocs allowed) ----------------------
__device__ __nv_bfloat16 g_q[(size_t)BB*WW*DD];   // [b][w][d], pre-scaled
__device__ __nv_bfloat16 g_k[(size_t)BB*WW*DD];   // [b][w][d]
__device__ __nv_bfloat16 g_v[(size_t)BB*CC*WW];   // [b][c][w]; later scaled by linv[j]

// ---- helpers --------------------------------------------------------------
__device__ __forceinline__ uint32_t smem_u32(const void* p) {
    uint32_t a;
    asm("{ .reg .u64 t; cvta.to.shared.u64 t, %1; cvt.u32.u64 %0, t; }"
        : "=r"(a) : "l"(p));
    return a;
}
__device__ __forceinline__ uint32_t bf2u(__nv_bfloat162 h) {
    return *reinterpret_cast<uint32_t*>(&h);
}

// ---- mma.sync m16n8k16 bf16 (A row-major, B col-major, f32 accum) ---------
__device__ __forceinline__ void mma_acc(float* d, const uint32_t* a,
                                        uint32_t b0, uint32_t b1) {
    asm volatile("mma.sync.aligned.m16n8k16.row.col.f32.bf16.bf16.f32 "
        "{%0,%1,%2,%3}, {%4,%5,%6,%7}, {%8,%9}, {%0,%1,%2,%3};"
        : "+f"(d[0]), "+f"(d[1]), "+f"(d[2]), "+f"(d[3])
        : "r"(a[0]), "r"(a[1]), "r"(a[2]), "r"(a[3]), "r"(b0), "r"(b1));
}
__device__ __forceinline__ void mma_z(float* d, const uint32_t* a,
                                      uint32_t b0, uint32_t b1) {
    asm volatile("mma.sync.aligned.m16n8k16.row.col.f32.bf16.bf16.f32 "
        "{%0,%1,%2,%3}, {%4,%5,%6,%7}, {%8,%9}, {%10,%10,%10,%10};"
        : "=f"(d[0]), "=f"(d[1]), "=f"(d[2]), "=f"(d[3])
        : "r"(a[0]), "r"(a[1]), "r"(a[2]), "r"(a[3]), "r"(b0), "r"(b1),
          "f"(0.0f));
}
#define LDMX4(v0, v1, v2, v3, addr) \
    asm volatile("ldmatrix.sync.aligned.m8n8.x4.shared.b16 {%0,%1,%2,%3}, [%4];" \
        : "=r"(v0), "=r"(v1), "=r"(v2), "=r"(v3) : "r"(addr))

// ---- cp.async -------------------------------------------------------------
#define CP16(dst, src) asm volatile("cp.async.cg.shared.global [%0], [%1], 16;" :: "r"(dst), "l"(src))
#define CP8(dst, src)  asm volatile("cp.async.ca.shared.global [%0], [%1], 8;"  :: "r"(dst), "l"(src))
#define CP_COMMIT()    asm volatile("cp.async.commit_group;" ::: "memory")
#define CP_WAIT0()     asm volatile("cp.async.wait_group 0;" ::: "memory")
#define CP_WAIT1()     asm volatile("cp.async.wait_group 1;" ::: "memory")

// ===========================================================================
// Kernel 1: projections via bf16 HMMA (R9 version — best measured config:
// 128-wide w tiles, 256 CTAs, weights staged once per CTA).
// ===========================================================================
#define SPX 272
#define OFX 0
#define OFW 34816
#define OFQ 69632
#define OFT 78336

__global__ void __launch_bounds__(256) k_proj(
    const float* __restrict__ x,
    const float* __restrict__ Wq, const float* __restrict__ bq,
    const float* __restrict__ Wk, const float* __restrict__ bk,
    const float* __restrict__ Wv, const float* __restrict__ bv)
{
    extern __shared__ __align__(16) char smc[];
    const int b   = blockIdx.y;
    const int w0  = blockIdx.x * 128;
    const int tid = threadIdx.x;
    const int wid = tid >> 5;
    const int lane = tid & 31;
    const int g = lane >> 2, t = lane & 3;

    for (int i = tid; i < 128*32; i += 256) {
        int r = i >> 5, cf = i & 31;
        float4 v = *(const float4*)(Wv + r*128 + cf*4);
        uint2 o;
        o.x = bf2u(__floats2bfloat162_rn(v.x, v.y));
        o.y = bf2u(__floats2bfloat162_rn(v.z, v.w));
        *(uint2*)(smc + OFW + r*SPX + cf*8) = o;
    }
    for (int i = tid; i < 32*32; i += 256) {
        int r = i >> 5, cf = i & 31;
        const float* src = (r < 16) ? (Wq + r*128 + cf*4) : (Wk + (r-16)*128 + cf*4);
        float4 v = *(const float4*)src;
        uint2 o;
        o.x = bf2u(__floats2bfloat162_rn(v.x, v.y));
        o.y = bf2u(__floats2bfloat162_rn(v.z, v.w));
        *(uint2*)(smc + OFQ + r*SPX + cf*8) = o;
    }
    {
        const int c = tid & 127, hf = tid >> 7;
        const float* xp = x + (size_t)(b*CC + c)*WW + w0 + hf*64;
        #pragma unroll
        for (int it = 0; it < 16; it++) {
            float4 v = *(const float4*)(xp + it*4);
            int w = hf*64 + it*4;
            *(__nv_bfloat16*)(smc + OFX + (w  )*SPX + c*2) = __float2bfloat16(v.x);
            *(__nv_bfloat16*)(smc + OFX + (w+1)*SPX + c*2) = __float2bfloat16(v.y);
            *(__nv_bfloat16*)(smc + OFX + (w+2)*SPX + c*2) = __float2bfloat16(v.z);
            *(__nv_bfloat16*)(smc + OFX + (w+3)*SPX + c*2) = __float2bfloat16(v.w);
        }
    }
    __syncthreads();

    {   // V GEMM
        const int mb = wid * 16;
        uint32_t A[8][4];
        #pragma unroll
        for (int kt = 0; kt < 8; kt++) {
            const char* r0 = smc + OFW + (mb + g)*SPX + kt*32 + t*4;
            const char* r1 = smc + OFW + (mb + g + 8)*SPX + kt*32 + t*4;
            A[kt][0] = *(const uint32_t*)r0;
            A[kt][1] = *(const uint32_t*)r1;
            A[kt][2] = *(const uint32_t*)(r0 + 16);
            A[kt][3] = *(const uint32_t*)(r1 + 16);
        }
        const float bias0 = bv[mb + g], bias1 = bv[mb + g + 8];
        #pragma unroll
        for (int nt = 0; nt < 16; nt++) {
            float acc[4] = {bias0, bias0, bias1, bias1};
            #pragma unroll
            for (int kt = 0; kt < 8; kt++) {
                const char* bp = smc + OFX + (nt*8 + g)*SPX + kt*32 + t*4;
                uint32_t b0 = *(const uint32_t*)bp;
                uint32_t b1 = *(const uint32_t*)(bp + 16);
                mma_acc(acc, A[kt], b0, b1);
            }
            const int wcol = w0 + nt*8 + 2*t;
            *(uint32_t*)(g_v + (size_t)(b*CC + mb + g)*WW + wcol) =
                bf2u(__floats2bfloat162_rn(acc[0], acc[1]));
            *(uint32_t*)(g_v + (size_t)(b*CC + mb + g + 8)*WW + wcol) =
                bf2u(__floats2bfloat162_rn(acc[2], acc[3]));
        }
    }

    {   // QK GEMM
        const int mt = wid & 1, ntb = (wid >> 1) * 4;
        uint32_t A[8][4];
        #pragma unroll
        for (int kt = 0; kt < 8; kt++) {
            const char* r0 = smc + OFQ + (mt*16 + g)*SPX + kt*32 + t*4;
            const char* r1 = smc + OFQ + (mt*16 + g + 8)*SPX + kt*32 + t*4;
            A[kt][0] = *(const uint32_t*)r0;
            A[kt][1] = *(const uint32_t*)r1;
            A[kt][2] = *(const uint32_t*)(r0 + 16);
            A[kt][3] = *(const uint32_t*)(r1 + 16);
        }
        const float* bias = mt ? bk : bq;
        const float bias0 = bias[g], bias1 = bias[g + 8];
        const float psc = mt ? 1.0f : QSCALE;
        #pragma unroll
        for (int nt = ntb; nt < ntb + 4; nt++) {
            float acc[4] = {bias0, bias0, bias1, bias1};
            #pragma unroll
            for (int kt = 0; kt < 8; kt++) {
                const char* bp = smc + OFX + (nt*8 + g)*SPX + kt*32 + t*4;
                uint32_t b0 = *(const uint32_t*)bp;
                uint32_t b1 = *(const uint32_t*)(bp + 16);
                mma_acc(acc, A[kt], b0, b1);
            }
            const int wcol = nt*8 + 2*t;
            *(uint32_t*)(smc + OFT + (mt*16 + g)*SPX + wcol*2) =
                bf2u(__floats2bfloat162_rn(acc[0]*psc, acc[1]*psc));
            *(uint32_t*)(smc + OFT + (mt*16 + g + 8)*SPX + wcol*2) =
                bf2u(__floats2bfloat162_rn(acc[2]*psc, acc[3]*psc));
        }
    }
    __syncthreads();

    {   // transpose qkT -> g_q/g_k [w][16]
        const int w = tid & 127, half = tid >> 7;
        uint32_t u[8];
        #pragma unroll
        for (int i = 0; i < 8; i++) {
            uint32_t lo = *(const uint16_t*)(smc + OFT + (half*16 + 2*i    )*SPX + w*2);
            uint32_t hi = *(const uint16_t*)(smc + OFT + (half*16 + 2*i + 1)*SPX + w*2);
            u[i] = lo | (hi << 16);
        }
        __nv_bfloat16* op = (half ? g_k : g_q) + (size_t)(b*WW + w0 + w)*DD;
        *(uint4*)op       = make_uint4(u[0], u[1], u[2], u[3]);
        *(uint4*)(op + 8) = make_uint4(u[4], u[5], u[6], u[7]);
    }
}

// ===========================================================================
// Kernel 2: row sums + fold 1/l into V. Warp-autonomous (R13, bug-fixed).
// ===========================================================================
#define SKD 48
__global__ void __launch_bounds__(256, 2) k_stats()
{
    __shared__ __align__(16) char smq[128*SKD];
    __shared__ __align__(16) char smk[8*2*16*SKD];
    __shared__ float partial[8][128];
    __shared__ float red[128];
    __shared__ uint32_t lpk[64];
    const uint32_t QS = smem_u32(smq);
    const uint32_t KB = smem_u32(smk);
    const int tid = threadIdx.x;
    const int wid = tid >> 5;
    const int lane = tid & 31;
    const int g = lane >> 2, t = lane & 3;
    const int b = blockIdx.y, j0 = blockIdx.x * 128;

    const uint32_t kw = KB + wid*(2*16*SKD);
    const uint32_t kldst = kw + (lane >> 1)*SKD + (lane & 1)*16;
    const uint32_t mlane16 = (uint32_t)((((lane >> 4)*8 + (lane & 7))*SKD)
                                        + ((lane >> 3) & 1)*16);

    {
        int r = tid >> 1, h = tid & 1;
        CP16(QS + r*SKD + h*16, (const char*)(g_q + (size_t)(b*WW + j0 + r)*DD) + h*16);
        CP16(kldst, (const char*)(g_k + (size_t)(b*WW + wid*16 + (lane >> 1))*DD)
                    + (lane & 1)*16);
    }
    CP_COMMIT(); CP_WAIT0();
    __syncthreads();

    uint32_t A[8][4];
    #pragma unroll
    for (int mt = 0; mt < 8; mt++) {
        const char* r0 = smq + (mt*16 + g)*SKD + t*4;
        const char* r1 = smq + (mt*16 + g + 8)*SKD + t*4;
        A[mt][0] = *(const uint32_t*)r0;
        A[mt][1] = *(const uint32_t*)r1;
        A[mt][2] = *(const uint32_t*)(r0 + 16);
        A[mt][3] = *(const uint32_t*)(r1 + 16);
    }

    float lacc[8][2];
    #pragma unroll
    for (int mt = 0; mt < 8; mt++) { lacc[mt][0] = 0.0f; lacc[mt][1] = 0.0f; }

    for (int it8 = 0; it8 < 4; it8++) {
        uint32_t acc01[8], acc23[8];
        #pragma unroll
        for (int mt = 0; mt < 8; mt++) { acc01[mt] = 0u; acc23[mt] = 0u; }
        #pragma unroll
        for (int i8 = 0; i8 < 8; i8++) {
            const int it = it8*8 + i8;
            if (it + 1 < 32) {
                CP16(kldst + (uint32_t)(((it + 1) & 1)*(16*SKD)),
                     (const char*)(g_k + (size_t)(b*WW + (it + 1)*128 + wid*16
                                                  + (lane >> 1))*DD) + (lane & 1)*16);
            }
            CP_COMMIT();
            CP_WAIT1();
            uint32_t v0, v1, v2, v3;
            LDMX4(v0, v1, v2, v3, kw + (uint32_t)((it & 1)*(16*SKD)) + mlane16);
            #pragma unroll
            for (int mt = 0; mt < 8; mt++) {
                float d[4];
                uint32_t h01, h23;
                mma_z(d, A[mt], v0, v1);
                asm("cvt.rn.f16x2.f32 %0, %1, %2;" : "=r"(h01) : "f"(d[1]), "f"(d[0]));
                asm("cvt.rn.f16x2.f32 %0, %1, %2;" : "=r"(h23) : "f"(d[3]), "f"(d[2]));
                asm("ex2.approx.f16x2 %0, %0;" : "+r"(h01));
                asm("ex2.approx.f16x2 %0, %0;" : "+r"(h23));
                asm("add.rn.f16x2 %0, %0, %1;" : "+r"(acc01[mt]) : "r"(h01));
                asm("add.rn.f16x2 %0, %0, %1;" : "+r"(acc23[mt]) : "r"(h23));
                mma_z(d, A[mt], v2, v3);
                asm("cvt.rn.f16x2.f32 %0, %1, %2;" : "=r"(h01) : "f"(d[1]), "f"(d[0]));
                asm("cvt.rn.f16x2.f32 %0, %1, %2;" : "=r"(h23) : "f"(d[3]), "f"(d[2]));
                asm("ex2.approx.f16x2 %0, %0;" : "+r"(h01));
                asm("ex2.approx.f16x2 %0, %0;" : "+r"(h23));
                asm("add.rn.f16x2 %0, %0, %1;" : "+r"(acc01[mt]) : "r"(h01));
                asm("add.rn.f16x2 %0, %0, %1;" : "+r"(acc23[mt]) : "r"(h23));
            }
        }
        #pragma unroll
        for (int mt = 0; mt < 8; mt++) {
            float f0, f1, f2, f3;
            asm("{.reg .f16 lo, hi; mov.b32 {lo, hi}, %2; cvt.f32.f16 %0, lo; cvt.f32.f16 %1, hi;}"
                : "=f"(f0), "=f"(f1) : "r"(acc01[mt]));
            asm("{.reg .f16 lo, hi; mov.b32 {lo, hi}, %2; cvt.f32.f16 %0, lo; cvt.f32.f16 %1, hi;}"
                : "=f"(f2), "=f"(f3) : "r"(acc23[mt]));
            lacc[mt][0] += f0 + f1;
            lacc[mt][1] += f2 + f3;
        }
    }

    #pragma unroll
    for (int mt = 0; mt < 8; mt++) {
        #pragma unroll
        for (int off = 1; off < 4; off <<= 1) {
            lacc[mt][0] += __shfl_down_sync(0xffffffffu, lacc[mt][0], off, 4);
            lacc[mt][1] += __shfl_down_sync(0xffffffffu, lacc[mt][1], off, 4);
        }
        if (t == 0) {
            partial[wid][mt*16 + g]     = lacc[mt][0];
            partial[wid][mt*16 + g + 8] = lacc[mt][1];
        }
    }
    __syncthreads();
    if (tid < 128) {
        float l = partial[0][tid] + partial[1][tid] + partial[2][tid] + partial[3][tid]
                + partial[4][tid] + partial[5][tid] + partial[6][tid] + partial[7][tid];
        red[tid] = 1.0f / l;
    }
    __syncthreads();
    if (tid < 64)
        lpk[tid] = bf2u(__floats2bfloat162_rn(red[2*tid], red[2*tid + 1]));
    __syncthreads();

    {
        const int chunk = tid & 15;
        const int cb    = tid >> 4;
        uint32_t s0 = lpk[chunk*4], s1 = lpk[chunk*4 + 1];
        uint32_t s2 = lpk[chunk*4 + 2], s3 = lpk[chunk*4 + 3];
        #pragma unroll
        for (int c = cb; c < 128; c += 16) {
            uint32_t* vp = (uint32_t*)(g_v + (size_t)(b*CC + c)*WW + j0 + chunk*8);
            uint4 v = *(uint4*)vp;
            asm("mul.rn.bf16x2 %0, %0, %1;" : "+r"(v.x) : "r"(s0));
            asm("mul.rn.bf16x2 %0, %0, %1;" : "+r"(v.y) : "r"(s1));
            asm("mul.rn.bf16x2 %0, %0, %1;" : "+r"(v.z) : "r"(s2));
            asm("mul.rn.bf16x2 %0, %0, %1;" : "+r"(v.w) : "r"(s3));
            *(uint4*)vp = v;
        }
    }
}

// ===========================================================================
// Kernel 3: context + residual. Main loop unchanged from R10; NEW epilogue
// stages acc through smem for fully coalesced 128B x-load/out-store.
// ===========================================================================
#define SPJ 144
#define OF_KS 0
#define OF_QR 6144
#define OF_VS 18432

__global__ void __launch_bounds__(256, 2) k_ctx(const float* __restrict__ x,
                                                float* __restrict__ out)
{
    extern __shared__ __align__(16) char smc[];
    const uint32_t smb = smem_u32(smc);
    const int tid = threadIdx.x;
    const int wid = tid >> 5;
    const int lane = tid & 31;
    const int g = lane >> 2, t = lane & 3;
    const int b = blockIdx.y, w0 = blockIdx.x * 128;

    {
        int r = tid >> 1, h = tid & 1;
        CP16(smb + OF_KS + r*SKD + h*16,
             (const char*)(g_k + (size_t)(b*WW + w0 + r)*DD) + h*16);
    }
    {
        int r = tid >> 2, h = tid & 3;
        CP8(smb + OF_QR + r*SKD + h*8,
            (const char*)(g_q + (size_t)(b*WW + r)*DD) + h*8);
        CP8(smb + OF_QR + 3072 + r*SKD + h*8,
            (const char*)(g_q + (size_t)(b*WW + 64 + r)*DD) + h*8);
    }
    #pragma unroll
    for (int i = 0; i < 4; i++) {
        int cid = tid + i*256;
        int c = cid >> 3, ch = cid & 7;
        CP16(smb + OF_VS + c*SPJ + ch*16,
             (const char*)(g_v + (size_t)(b*CC + c)*WW) + ch*16);
    }
    CP_COMMIT(); CP_WAIT0();
    __syncthreads();

    uint32_t ak[4];
    {
        const char* r0 = smc + OF_KS + (wid*16 + g)*SKD + t*4;
        const char* r1 = smc + OF_KS + (wid*16 + g + 8)*SKD + t*4;
        ak[0] = *(const uint32_t*)r0;
        ak[1] = *(const uint32_t*)r1;
        ak[2] = *(const uint32_t*)(r0 + 16);
        ak[3] = *(const uint32_t*)(r1 + 16);
    }

    const uint32_t vlane = (uint32_t)((((lane >> 4)*8 + (lane & 7))*SPJ)
                                      + ((lane >> 3) & 1)*16);
    const uint32_t qlane = (uint32_t)((((lane >> 4)*8 + (lane & 7))*SKD)
                                      + ((lane >> 3) & 1)*16);

    float acc[16][4];
    #pragma unroll
    for (int ct = 0; ct < 16; ct++)
        #pragma unroll
        for (int e = 0; e < 4; e++) acc[ct][e] = 0.0f;

    for (int jt = 0; jt < 64; jt++) {
        if (jt + 2 < 64) {
            int r = tid >> 2, h = tid & 3;
            CP8(smb + OF_QR + ((jt + 2) & 3)*3072 + r*SKD + h*8,
                (const char*)(g_q + (size_t)(b*WW + (jt + 2)*64 + r)*DD) + h*8);
        }
        if (jt + 1 < 64) {
            #pragma unroll
            for (int i = 0; i < 4; i++) {
                int cid = tid + i*256;
                int c = cid >> 3, ch = cid & 7;
                CP16(smb + OF_VS + ((jt + 1) & 1)*18432 + c*SPJ + ch*16,
                     (const char*)(g_v + (size_t)(b*CC + c)*WW + (jt + 1)*64) + ch*16);
            }
        }
        CP_COMMIT();

        const uint32_t qb = smb + OF_QR + (jt & 3)*3072 + qlane;
        const uint32_t vb = smb + OF_VS + (jt & 1)*18432 + vlane;

        #pragma unroll
        for (int ks = 0; ks < 4; ks++) {
            uint32_t A[4];
            {
                uint32_t q0, q1, q2, q3;
                LDMX4(q0, q1, q2, q3, qb + (uint32_t)(ks*(16*SKD)));
                float d[4];
                mma_z(d, ak, q0, q1);
                asm("cvt.rn.bf16x2.f32 %0, %1, %2;" : "=r"(A[0]) : "f"(d[1]), "f"(d[0]));
                asm("cvt.rn.bf16x2.f32 %0, %1, %2;" : "=r"(A[1]) : "f"(d[3]), "f"(d[2]));
                mma_z(d, ak, q2, q3);
                asm("cvt.rn.bf16x2.f32 %0, %1, %2;" : "=r"(A[2]) : "f"(d[1]), "f"(d[0]));
                asm("cvt.rn.bf16x2.f32 %0, %1, %2;" : "=r"(A[3]) : "f"(d[3]), "f"(d[2]));
                asm("ex2.approx.ftz.bf16x2 %0, %0;" : "+r"(A[0]));
                asm("ex2.approx.ftz.bf16x2 %0, %0;" : "+r"(A[1]));
                asm("ex2.approx.ftz.bf16x2 %0, %0;" : "+r"(A[2]));
                asm("ex2.approx.ftz.bf16x2 %0, %0;" : "+r"(A[3]));
            }
            #pragma unroll
            for (int cp = 0; cp < 8; cp++) {
                uint32_t v0, v1, v2, v3;
                uint32_t ad = vb + (uint32_t)(cp*(16*SPJ) + ks*32);
                LDMX4(v0, v1, v2, v3, ad);
                mma_acc(acc[2*cp],     A, v0, v1);
                mma_acc(acc[2*cp + 1], A, v2, v3);
            }
        }
        CP_WAIT0();
        __syncthreads();
    }

    // ---- epilogue: stage acc -> smem (padded), coalesced out = acc + x ----
    float* es = (float*)smc;             // [64][132] f32 = 33792 B
    #pragma unroll
    for (int p = 0; p < 2; p++) {
        __syncthreads();
        #pragma unroll
        for (int ct8 = 0; ct8 < 8; ct8++) {
            const int ct = p*8 + ct8;
            const int cr = ct8*8 + 2*t;          // c - p*64 (even)
            const int wl = wid*16 + g;
            es[(cr    )*132 + wl    ] = acc[ct][0];
            es[(cr + 1)*132 + wl    ] = acc[ct][1];
            es[(cr    )*132 + wl + 8] = acc[ct][2];
            es[(cr + 1)*132 + wl + 8] = acc[ct][3];
        }
        __syncthreads();
        const int c0 = tid >> 3;                 // 0..31
        const int l8 = tid & 7;
        #pragma unroll
        for (int cc = 0; cc < 2; cc++) {
            const int cr = c0 + cc*32;
            const size_t gbase = (size_t)(b*CC + p*64 + cr)*WW + w0;
            #pragma unroll
            for (int i = 0; i < 4; i++) {
                const int w = (l8 + i*8)*4;
                float4 a  = *(float4*)&es[cr*132 + w];
                float4 xv = *(const float4*)(x + gbase + w);
                *(float4*)(out + gbase + w) =
                    make_float4(a.x + xv.x, a.y + xv.y, a.z + xv.z, a.w + xv.w);
            }
        }
    }
}

// ===========================================================================
extern "C" void kernel_launch(void* const* d_in, const int* in_sizes, int n_in,
                              void* d_out, int out_size)
{
    const float* x  = (const float*)d_in[0];
    const float* Wq = (const float*)d_in[1];
    const float* bq = (const float*)d_in[2];
    const float* Wk = (const float*)d_in[3];
    const float* bk = (const float*)d_in[4];
    const float* Wv = (const float*)d_in[5];
    const float* bv = (const float*)d_in[6];
    float* out = (float*)d_out;

    const int smem_proj = 87040;
    const int smem_ctx  = 55296;
    cudaFuncSetAttribute(k_proj, cudaFuncAttributeMaxDynamicSharedMemorySize, smem_proj);
    cudaFuncSetAttribute(k_ctx,  cudaFuncAttributeMaxDynamicSharedMemorySize, smem_ctx);

    dim3 g(WW/128, BB);
    k_proj <<<g, 256, smem_proj>>>(x, Wq, bq, Wk, bk, Wv, bv);
    k_stats<<<g, 256>>>();
    k_ctx  <<<g, 256, smem_ctx>>>(x, out);
}

// round 15
// speedup vs baseline: 1.0453x; 1.0164x over previous
#include <cuda_runtime.h>
#include <cuda_bf16.h>
#include <cstdint>

#define BB 8
#define CC 128
#define WW 4096
#define DD 16

// 0.25 (= D^-0.5) * log2(e): folded into q so softmax uses exp2 directly.
#define QSCALE 0.3606737602222409f

typedef unsigned long long ull;

// ---- scratch (__device__ globals; no allocs allowed) ----------------------
__device__ __nv_bfloat16 g_q[(size_t)BB*WW*DD];   // [b][w][d], pre-scaled
__device__ __nv_bfloat16 g_k[(size_t)BB*WW*DD];   // [b][w][d]
__device__ __nv_bfloat16 g_v[(size_t)BB*CC*WW];   // [b][c][w]; later scaled by linv[j]
__device__ int g_ctr_s, g_ctr_c;                  // work-steal counters

// ---- helpers --------------------------------------------------------------
__device__ __forceinline__ uint32_t smem_u32(const void* p) {
    uint32_t a;
    asm("{ .reg .u64 t; cvta.to.shared.u64 t, %1; cvt.u32.u64 %0, t; }"
        : "=r"(a) : "l"(p));
    return a;
}
__device__ __forceinline__ uint32_t bf2u(__nv_bfloat162 h) {
    return *reinterpret_cast<uint32_t*>(&h);
}

// ---- mma.sync m16n8k16 bf16 (A row-major, B col-major, f32 accum) ---------
__device__ __forceinline__ void mma_acc(float* d, const uint32_t* a,
                                        uint32_t b0, uint32_t b1) {
    asm volatile("mma.sync.aligned.m16n8k16.row.col.f32.bf16.bf16.f32 "
        "{%0,%1,%2,%3}, {%4,%5,%6,%7}, {%8,%9}, {%0,%1,%2,%3};"
        : "+f"(d[0]), "+f"(d[1]), "+f"(d[2]), "+f"(d[3])
        : "r"(a[0]), "r"(a[1]), "r"(a[2]), "r"(a[3]), "r"(b0), "r"(b1));
}
__device__ __forceinline__ void mma_z(float* d, const uint32_t* a,
                                      uint32_t b0, uint32_t b1) {
    asm volatile("mma.sync.aligned.m16n8k16.row.col.f32.bf16.bf16.f32 "
        "{%0,%1,%2,%3}, {%4,%5,%6,%7}, {%8,%9}, {%10,%10,%10,%10};"
        : "=f"(d[0]), "=f"(d[1]), "=f"(d[2]), "=f"(d[3])
        : "r"(a[0]), "r"(a[1]), "r"(a[2]), "r"(a[3]), "r"(b0), "r"(b1),
          "f"(0.0f));
}
#define LDMX4(v0, v1, v2, v3, addr) \
    asm volatile("ldmatrix.sync.aligned.m8n8.x4.shared.b16 {%0,%1,%2,%3}, [%4];" \
        : "=r"(v0), "=r"(v1), "=r"(v2), "=r"(v3) : "r"(addr))

// ---- cp.async -------------------------------------------------------------
#define CP16(dst, src) asm volatile("cp.async.cg.shared.global [%0], [%1], 16;" :: "r"(dst), "l"(src))
#define CP8(dst, src)  asm volatile("cp.async.ca.shared.global [%0], [%1], 8;"  :: "r"(dst), "l"(src))
#define CP_COMMIT()    asm volatile("cp.async.commit_group;" ::: "memory")
#define CP_WAIT0()     asm volatile("cp.async.wait_group 0;" ::: "memory")
#define CP_WAIT1()     asm volatile("cp.async.wait_group 1;" ::: "memory")

// ===========================================================================
// Kernel 1: projections via bf16 HMMA (R9/R14 version — best measured).
// Also zeroes the work-steal counters for this launch.
// ===========================================================================
#define SPX 272
#define OFX 0
#define OFW 34816
#define OFQ 69632
#define OFT 78336

__global__ void __launch_bounds__(256) k_proj(
    const float* __restrict__ x,
    const float* __restrict__ Wq, const float* __restrict__ bq,
    const float* __restrict__ Wk, const float* __restrict__ bk,
    const float* __restrict__ Wv, const float* __restrict__ bv)
{
    extern __shared__ __align__(16) char smc[];
    const int b   = blockIdx.y;
    const int w0  = blockIdx.x * 128;
    const int tid = threadIdx.x;
    const int wid = tid >> 5;
    const int lane = tid & 31;
    const int g = lane >> 2, t = lane & 3;

    if (blockIdx.x == 0 && blockIdx.y == 0 && tid == 0) {
        g_ctr_s = 0;
        g_ctr_c = 0;
    }

    for (int i = tid; i < 128*32; i += 256) {
        int r = i >> 5, cf = i & 31;
        float4 v = *(const float4*)(Wv + r*128 + cf*4);
        uint2 o;
        o.x = bf2u(__floats2bfloat162_rn(v.x, v.y));
        o.y = bf2u(__floats2bfloat162_rn(v.z, v.w));
        *(uint2*)(smc + OFW + r*SPX + cf*8) = o;
    }
    for (int i = tid; i < 32*32; i += 256) {
        int r = i >> 5, cf = i & 31;
        const float* src = (r < 16) ? (Wq + r*128 + cf*4) : (Wk + (r-16)*128 + cf*4);
        float4 v = *(const float4*)src;
        uint2 o;
        o.x = bf2u(__floats2bfloat162_rn(v.x, v.y));
        o.y = bf2u(__floats2bfloat162_rn(v.z, v.w));
        *(uint2*)(smc + OFQ + r*SPX + cf*8) = o;
    }
    {
        const int c = tid & 127, hf = tid >> 7;
        const float* xp = x + (size_t)(b*CC + c)*WW + w0 + hf*64;
        #pragma unroll
        for (int it = 0; it < 16; it++) {
            float4 v = *(const float4*)(xp + it*4);
            int w = hf*64 + it*4;
            *(__nv_bfloat16*)(smc + OFX + (w  )*SPX + c*2) = __float2bfloat16(v.x);
            *(__nv_bfloat16*)(smc + OFX + (w+1)*SPX + c*2) = __float2bfloat16(v.y);
            *(__nv_bfloat16*)(smc + OFX + (w+2)*SPX + c*2) = __float2bfloat16(v.z);
            *(__nv_bfloat16*)(smc + OFX + (w+3)*SPX + c*2) = __float2bfloat16(v.w);
        }
    }
    __syncthreads();

    {   // V GEMM
        const int mb = wid * 16;
        uint32_t A[8][4];
        #pragma unroll
        for (int kt = 0; kt < 8; kt++) {
            const char* r0 = smc + OFW + (mb + g)*SPX + kt*32 + t*4;
            const char* r1 = smc + OFW + (mb + g + 8)*SPX + kt*32 + t*4;
            A[kt][0] = *(const uint32_t*)r0;
            A[kt][1] = *(const uint32_t*)r1;
            A[kt][2] = *(const uint32_t*)(r0 + 16);
            A[kt][3] = *(const uint32_t*)(r1 + 16);
        }
        const float bias0 = bv[mb + g], bias1 = bv[mb + g + 8];
        #pragma unroll
        for (int nt = 0; nt < 16; nt++) {
            float acc[4] = {bias0, bias0, bias1, bias1};
            #pragma unroll
            for (int kt = 0; kt < 8; kt++) {
                const char* bp = smc + OFX + (nt*8 + g)*SPX + kt*32 + t*4;
                uint32_t b0 = *(const uint32_t*)bp;
                uint32_t b1 = *(const uint32_t*)(bp + 16);
                mma_acc(acc, A[kt], b0, b1);
            }
            const int wcol = w0 + nt*8 + 2*t;
            *(uint32_t*)(g_v + (size_t)(b*CC + mb + g)*WW + wcol) =
                bf2u(__floats2bfloat162_rn(acc[0], acc[1]));
            *(uint32_t*)(g_v + (size_t)(b*CC + mb + g + 8)*WW + wcol) =
                bf2u(__floats2bfloat162_rn(acc[2], acc[3]));
        }
    }

    {   // QK GEMM
        const int mt = wid & 1, ntb = (wid >> 1) * 4;
        uint32_t A[8][4];
        #pragma unroll
        for (int kt = 0; kt < 8; kt++) {
            const char* r0 = smc + OFQ + (mt*16 + g)*SPX + kt*32 + t*4;
            const char* r1 = smc + OFQ + (mt*16 + g + 8)*SPX + kt*32 + t*4;
            A[kt][0] = *(const uint32_t*)r0;
            A[kt][1] = *(const uint32_t*)r1;
            A[kt][2] = *(const uint32_t*)(r0 + 16);
            A[kt][3] = *(const uint32_t*)(r1 + 16);
        }
        const float* bias = mt ? bk : bq;
        const float bias0 = bias[g], bias1 = bias[g + 8];
        const float psc = mt ? 1.0f : QSCALE;
        #pragma unroll
        for (int nt = ntb; nt < ntb + 4; nt++) {
            float acc[4] = {bias0, bias0, bias1, bias1};
            #pragma unroll
            for (int kt = 0; kt < 8; kt++) {
                const char* bp = smc + OFX + (nt*8 + g)*SPX + kt*32 + t*4;
                uint32_t b0 = *(const uint32_t*)bp;
                uint32_t b1 = *(const uint32_t*)(bp + 16);
                mma_acc(acc, A[kt], b0, b1);
            }
            const int wcol = nt*8 + 2*t;
            *(uint32_t*)(smc + OFT + (mt*16 + g)*SPX + wcol*2) =
                bf2u(__floats2bfloat162_rn(acc[0]*psc, acc[1]*psc));
            *(uint32_t*)(smc + OFT + (mt*16 + g + 8)*SPX + wcol*2) =
                bf2u(__floats2bfloat162_rn(acc[2]*psc, acc[3]*psc));
        }
    }
    __syncthreads();

    {   // transpose qkT -> g_q/g_k [w][16]
        const int w = tid & 127, half = tid >> 7;
        uint32_t u[8];
        #pragma unroll
        for (int i = 0; i < 8; i++) {
            uint32_t lo = *(const uint16_t*)(smc + OFT + (half*16 + 2*i    )*SPX + w*2);
            uint32_t hi = *(const uint16_t*)(smc + OFT + (half*16 + 2*i + 1)*SPX + w*2);
            u[i] = lo | (hi << 16);
        }
        __nv_bfloat16* op = (half ? g_k : g_q) + (size_t)(b*WW + w0 + w)*DD;
        *(uint4*)op       = make_uint4(u[0], u[1], u[2], u[3]);
        *(uint4*)(op + 8) = make_uint4(u[4], u[5], u[6], u[7]);
    }
}

// ===========================================================================
// Kernel 2: row sums + fold 1/l into V. Warp-autonomous, now PERSISTENT:
// 296 CTAs work-steal 256 (b, j-tile) items -> balanced per-SM load.
// ===========================================================================
#define SKD 48
__global__ void __launch_bounds__(256, 2) k_stats()
{
    __shared__ __align__(16) char smq[128*SKD];
    __shared__ __align__(16) char smk[8*2*16*SKD];
    __shared__ float partial[8][128];
    __shared__ float red[128];
    __shared__ uint32_t lpk[64];
    __shared__ int s_item;
    const uint32_t QS = smem_u32(smq);
    const uint32_t KB = smem_u32(smk);
    const int tid = threadIdx.x;
    const int wid = tid >> 5;
    const int lane = tid & 31;
    const int g = lane >> 2, t = lane & 3;

    const uint32_t kw = KB + wid*(2*16*SKD);
    const uint32_t kldst = kw + (lane >> 1)*SKD + (lane & 1)*16;
    const uint32_t mlane16 = (uint32_t)((((lane >> 4)*8 + (lane & 7))*SKD)
                                        + ((lane >> 3) & 1)*16);

    while (true) {
        if (tid == 0) s_item = atomicAdd(&g_ctr_s, 1);
        __syncthreads();
        const int item = s_item;
        __syncthreads();
        if (item >= 256) return;
        const int b = item >> 5, j0 = (item & 31) << 7;

        {
            int r = tid >> 1, h = tid & 1;
            CP16(QS + r*SKD + h*16, (const char*)(g_q + (size_t)(b*WW + j0 + r)*DD) + h*16);
            CP16(kldst, (const char*)(g_k + (size_t)(b*WW + wid*16 + (lane >> 1))*DD)
                        + (lane & 1)*16);
        }
        CP_COMMIT(); CP_WAIT0();
        __syncthreads();

        uint32_t A[8][4];
        #pragma unroll
        for (int mt = 0; mt < 8; mt++) {
            const char* r0 = smq + (mt*16 + g)*SKD + t*4;
            const char* r1 = smq + (mt*16 + g + 8)*SKD + t*4;
            A[mt][0] = *(const uint32_t*)r0;
            A[mt][1] = *(const uint32_t*)r1;
            A[mt][2] = *(const uint32_t*)(r0 + 16);
            A[mt][3] = *(const uint32_t*)(r1 + 16);
        }

        float lacc[8][2];
        #pragma unroll
        for (int mt = 0; mt < 8; mt++) { lacc[mt][0] = 0.0f; lacc[mt][1] = 0.0f; }

        for (int it8 = 0; it8 < 4; it8++) {
            uint32_t acc01[8], acc23[8];
            #pragma unroll
            for (int mt = 0; mt < 8; mt++) { acc01[mt] = 0u; acc23[mt] = 0u; }
            #pragma unroll
            for (int i8 = 0; i8 < 8; i8++) {
                const int it = it8*8 + i8;
                if (it + 1 < 32) {
                    CP16(kldst + (uint32_t)(((it + 1) & 1)*(16*SKD)),
                         (const char*)(g_k + (size_t)(b*WW + (it + 1)*128 + wid*16
                                                      + (lane >> 1))*DD) + (lane & 1)*16);
                }
                CP_COMMIT();
                CP_WAIT1();
                uint32_t v0, v1, v2, v3;
                LDMX4(v0, v1, v2, v3, kw + (uint32_t)((it & 1)*(16*SKD)) + mlane16);
                #pragma unroll
                for (int mt = 0; mt < 8; mt++) {
                    float d[4];
                    uint32_t h01, h23;
                    mma_z(d, A[mt], v0, v1);
                    asm("cvt.rn.f16x2.f32 %0, %1, %2;" : "=r"(h01) : "f"(d[1]), "f"(d[0]));
                    asm("cvt.rn.f16x2.f32 %0, %1, %2;" : "=r"(h23) : "f"(d[3]), "f"(d[2]));
                    asm("ex2.approx.f16x2 %0, %0;" : "+r"(h01));
                    asm("ex2.approx.f16x2 %0, %0;" : "+r"(h23));
                    asm("add.rn.f16x2 %0, %0, %1;" : "+r"(acc01[mt]) : "r"(h01));
                    asm("add.rn.f16x2 %0, %0, %1;" : "+r"(acc23[mt]) : "r"(h23));
                    mma_z(d, A[mt], v2, v3);
                    asm("cvt.rn.f16x2.f32 %0, %1, %2;" : "=r"(h01) : "f"(d[1]), "f"(d[0]));
                    asm("cvt.rn.f16x2.f32 %0, %1, %2;" : "=r"(h23) : "f"(d[3]), "f"(d[2]));
                    asm("ex2.approx.f16x2 %0, %0;" : "+r"(h01));
                    asm("ex2.approx.f16x2 %0, %0;" : "+r"(h23));
                    asm("add.rn.f16x2 %0, %0, %1;" : "+r"(acc01[mt]) : "r"(h01));
                    asm("add.rn.f16x2 %0, %0, %1;" : "+r"(acc23[mt]) : "r"(h23));
                }
            }
            #pragma unroll
            for (int mt = 0; mt < 8; mt++) {
                float f0, f1, f2, f3;
                asm("{.reg .f16 lo, hi; mov.b32 {lo, hi}, %2; cvt.f32.f16 %0, lo; cvt.f32.f16 %1, hi;}"
                    : "=f"(f0), "=f"(f1) : "r"(acc01[mt]));
                asm("{.reg .f16 lo, hi; mov.b32 {lo, hi}, %2; cvt.f32.f16 %0, lo; cvt.f32.f16 %1, hi;}"
                    : "=f"(f2), "=f"(f3) : "r"(acc23[mt]));
                lacc[mt][0] += f0 + f1;
                lacc[mt][1] += f2 + f3;
            }
        }

        #pragma unroll
        for (int mt = 0; mt < 8; mt++) {
            #pragma unroll
            for (int off = 1; off < 4; off <<= 1) {
                lacc[mt][0] += __shfl_down_sync(0xffffffffu, lacc[mt][0], off, 4);
                lacc[mt][1] += __shfl_down_sync(0xffffffffu, lacc[mt][1], off, 4);
            }
            if (t == 0) {
                partial[wid][mt*16 + g]     = lacc[mt][0];
                partial[wid][mt*16 + g + 8] = lacc[mt][1];
            }
        }
        __syncthreads();
        if (tid < 128) {
            float l = partial[0][tid] + partial[1][tid] + partial[2][tid] + partial[3][tid]
                    + partial[4][tid] + partial[5][tid] + partial[6][tid] + partial[7][tid];
            red[tid] = 1.0f / l;
        }
        __syncthreads();
        if (tid < 64)
            lpk[tid] = bf2u(__floats2bfloat162_rn(red[2*tid], red[2*tid + 1]));
        __syncthreads();

        {
            const int chunk = tid & 15;
            const int cb    = tid >> 4;
            uint32_t s0 = lpk[chunk*4], s1 = lpk[chunk*4 + 1];
            uint32_t s2 = lpk[chunk*4 + 2], s3 = lpk[chunk*4 + 3];
            #pragma unroll
            for (int c = cb; c < 128; c += 16) {
                uint32_t* vp = (uint32_t*)(g_v + (size_t)(b*CC + c)*WW + j0 + chunk*8);
                uint4 v = *(uint4*)vp;
                asm("mul.rn.bf16x2 %0, %0, %1;" : "+r"(v.x) : "r"(s0));
                asm("mul.rn.bf16x2 %0, %0, %1;" : "+r"(v.y) : "r"(s1));
                asm("mul.rn.bf16x2 %0, %0, %1;" : "+r"(v.z) : "r"(s2));
                asm("mul.rn.bf16x2 %0, %0, %1;" : "+r"(v.w) : "r"(s3));
                *(uint4*)vp = v;
            }
        }
        __syncthreads();   // smem safe for next item
    }
}

// ===========================================================================
// Kernel 3: context + residual. PERSISTENT: 296 CTAs work-steal 256
// (b, w-tile) items. Body = R14 (register-P, ldmatrix, staged epilogue).
// ===========================================================================
#define SPJ 144
#define OF_KS 0
#define OF_QR 6144
#define OF_VS 18432

__global__ void __launch_bounds__(256, 2) k_ctx(const float* __restrict__ x,
                                                float* __restrict__ out)
{
    extern __shared__ __align__(16) char smc[];
    __shared__ int s_item;
    const uint32_t smb = smem_u32(smc);
    const int tid = threadIdx.x;
    const int wid = tid >> 5;
    const int lane = tid & 31;
    const int g = lane >> 2, t = lane & 3;

    const uint32_t vlane = (uint32_t)((((lane >> 4)*8 + (lane & 7))*SPJ)
                                      + ((lane >> 3) & 1)*16);
    const uint32_t qlane = (uint32_t)((((lane >> 4)*8 + (lane & 7))*SKD)
                                      + ((lane >> 3) & 1)*16);

    while (true) {
        if (tid == 0) s_item = atomicAdd(&g_ctr_c, 1);
        __syncthreads();
        const int item = s_item;
        __syncthreads();
        if (item >= 256) return;
        const int b = item >> 5, w0 = (item & 31) << 7;

        {
            int r = tid >> 1, h = tid & 1;
            CP16(smb + OF_KS + r*SKD + h*16,
                 (const char*)(g_k + (size_t)(b*WW + w0 + r)*DD) + h*16);
        }
        {
            int r = tid >> 2, h = tid & 3;
            CP8(smb + OF_QR + r*SKD + h*8,
                (const char*)(g_q + (size_t)(b*WW + r)*DD) + h*8);
            CP8(smb + OF_QR + 3072 + r*SKD + h*8,
                (const char*)(g_q + (size_t)(b*WW + 64 + r)*DD) + h*8);
        }
        #pragma unroll
        for (int i = 0; i < 4; i++) {
            int cid = tid + i*256;
            int c = cid >> 3, ch = cid & 7;
            CP16(smb + OF_VS + c*SPJ + ch*16,
                 (const char*)(g_v + (size_t)(b*CC + c)*WW) + ch*16);
        }
        CP_COMMIT(); CP_WAIT0();
        __syncthreads();

        uint32_t ak[4];
        {
            const char* r0 = smc + OF_KS + (wid*16 + g)*SKD + t*4;
            const char* r1 = smc + OF_KS + (wid*16 + g + 8)*SKD + t*4;
            ak[0] = *(const uint32_t*)r0;
            ak[1] = *(const uint32_t*)r1;
            ak[2] = *(const uint32_t*)(r0 + 16);
            ak[3] = *(const uint32_t*)(r1 + 16);
        }

        float acc[16][4];
        #pragma unroll
        for (int ct = 0; ct < 16; ct++)
            #pragma unroll
            for (int e = 0; e < 4; e++) acc[ct][e] = 0.0f;

        for (int jt = 0; jt < 64; jt++) {
            if (jt + 2 < 64) {
                int r = tid >> 2, h = tid & 3;
                CP8(smb + OF_QR + ((jt + 2) & 3)*3072 + r*SKD + h*8,
                    (const char*)(g_q + (size_t)(b*WW + (jt + 2)*64 + r)*DD) + h*8);
            }
            if (jt + 1 < 64) {
                #pragma unroll
                for (int i = 0; i < 4; i++) {
                    int cid = tid + i*256;
                    int c = cid >> 3, ch = cid & 7;
                    CP16(smb + OF_VS + ((jt + 1) & 1)*18432 + c*SPJ + ch*16,
                         (const char*)(g_v + (size_t)(b*CC + c)*WW + (jt + 1)*64) + ch*16);
                }
            }
            CP_COMMIT();

            const uint32_t qb = smb + OF_QR + (jt & 3)*3072 + qlane;
            const uint32_t vb = smb + OF_VS + (jt & 1)*18432 + vlane;

            #pragma unroll
            for (int ks = 0; ks < 4; ks++) {
                uint32_t A[4];
                {
                    uint32_t q0, q1, q2, q3;
                    LDMX4(q0, q1, q2, q3, qb + (uint32_t)(ks*(16*SKD)));
                    float d[4];
                    mma_z(d, ak, q0, q1);
                    asm("cvt.rn.bf16x2.f32 %0, %1, %2;" : "=r"(A[0]) : "f"(d[1]), "f"(d[0]));
                    asm("cvt.rn.bf16x2.f32 %0, %1, %2;" : "=r"(A[1]) : "f"(d[3]), "f"(d[2]));
                    mma_z(d, ak, q2, q3);
                    asm("cvt.rn.bf16x2.f32 %0, %1, %2;" : "=r"(A[2]) : "f"(d[1]), "f"(d[0]));
                    asm("cvt.rn.bf16x2.f32 %0, %1, %2;" : "=r"(A[3]) : "f"(d[3]), "f"(d[2]));
                    asm("ex2.approx.ftz.bf16x2 %0, %0;" : "+r"(A[0]));
                    asm("ex2.approx.ftz.bf16x2 %0, %0;" : "+r"(A[1]));
                    asm("ex2.approx.ftz.bf16x2 %0, %0;" : "+r"(A[2]));
                    asm("ex2.approx.ftz.bf16x2 %0, %0;" : "+r"(A[3]));
                }
                #pragma unroll
                for (int cp = 0; cp < 8; cp++) {
                    uint32_t v0, v1, v2, v3;
                    uint32_t ad = vb + (uint32_t)(cp*(16*SPJ) + ks*32);
                    LDMX4(v0, v1, v2, v3, ad);
                    mma_acc(acc[2*cp],     A, v0, v1);
                    mma_acc(acc[2*cp + 1], A, v2, v3);
                }
            }
            CP_WAIT0();
            __syncthreads();
        }

        // ---- epilogue: stage acc -> smem, coalesced out = acc + x ----
        float* es = (float*)smc;
        #pragma unroll
        for (int p = 0; p < 2; p++) {
            __syncthreads();
            #pragma unroll
            for (int ct8 = 0; ct8 < 8; ct8++) {
                const int ct = p*8 + ct8;
                const int cr = ct8*8 + 2*t;
                const int wl = wid*16 + g;
                es[(cr    )*132 + wl    ] = acc[ct][0];
                es[(cr + 1)*132 + wl    ] = acc[ct][1];
                es[(cr    )*132 + wl + 8] = acc[ct][2];
                es[(cr + 1)*132 + wl + 8] = acc[ct][3];
            }
            __syncthreads();
            const int c0 = tid >> 3;
            const int l8 = tid & 7;
            #pragma unroll
            for (int cc = 0; cc < 2; cc++) {
                const int cr = c0 + cc*32;
                const size_t gbase = (size_t)(b*CC + p*64 + cr)*WW + w0;
                #pragma unroll
                for (int i = 0; i < 4; i++) {
                    const int w = (l8 + i*8)*4;
                    float4 a  = *(float4*)&es[cr*132 + w];
                    float4 xv = *(const float4*)(x + gbase + w);
                    *(float4*)(out + gbase + w) =
                        make_float4(a.x + xv.x, a.y + xv.y, a.z + xv.z, a.w + xv.w);
                }
            }
        }
        __syncthreads();   // es region aliases next item's tile buffers
    }
}

// ===========================================================================
extern "C" void kernel_launch(void* const* d_in, const int* in_sizes, int n_in,
                              void* d_out, int out_size)
{
    const float* x  = (const float*)d_in[0];
    const float* Wq = (const float*)d_in[1];
    const float* bq = (const float*)d_in[2];
    const float* Wk = (const float*)d_in[3];
    const float* bk = (const float*)d_in[4];
    const float* Wv = (const float*)d_in[5];
    const float* bv = (const float*)d_in[6];
    float* out = (float*)d_out;

    const int smem_proj = 87040;
    const int smem_ctx  = 55296;
    cudaFuncSetAttribute(k_proj, cudaFuncAttributeMaxDynamicSharedMemorySize, smem_proj);
    cudaFuncSetAttribute(k_ctx,  cudaFuncAttributeMaxDynamicSharedMemorySize, smem_ctx);

    dim3 g(WW/128, BB);
    k_proj <<<g, 256, smem_proj>>>(x, Wq, bq, Wk, bk, Wv, bv);
    k_stats<<<296, 256>>>();
    k_ctx  <<<296, 256, smem_ctx>>>(x, out);
}